// round 17
// baseline (speedup 1.0000x reference)
#include <cuda_runtime.h>
#include <cuda_bf16.h>
#include <cstdint>

// Problem constants
#define BB 128
#define DD 2048
#define NN 2048
#define TT 64
#define MM (BB * TT)   // 8192 rows of the GEMM

// FROZEN NUMERICS (validated R9/R12/R16, rel_err 6.355139e-4):
//   psp[m,n] = fold over 64-wide k-chunks (plain fp32 add per boundary),
//   ascending-k fp32 FMA chain within each chunk, bias added last, then
//   op-by-op rounded LIF scan. f32x2 packed ops are bit-identical per lane.
//   Any change to this per-output op order is a correctness regression.

typedef unsigned long long ull;

// ---- packed fp32x2 helpers (Blackwell; lane-wise IEEE fp32 rn) ----
#define FMA2(d, a, b) \
    asm("fma.rn.f32x2 %0, %1, %2, %0;" : "+l"(d) : "l"(a), "l"(b))
#define ADD2(d, a, b) \
    asm("add.rn.f32x2 %0, %1, %2;" : "=l"(d) : "l"(a), "l"(b))
#define PACK2(d, lo, hi) \
    asm("mov.b64 %0, {%1, %2};" : "=l"(d) : "r"(__float_as_uint(lo)), "r"(__float_as_uint(hi)))
#define UNPACK2(lo, hi, s) \
    do { unsigned int _ulo, _uhi; \
         asm("mov.b64 {%0, %1}, %2;" : "=r"(_ulo), "=r"(_uhi) : "l"(s)); \
         lo = __uint_as_float(_ulo); hi = __uint_as_float(_uhi); } while (0)

// ---------------------------------------------------------------------------
// Fused GEMM + LIF scan, 512 threads/CTA (16 warps: 4/SMSP for latency cover).
//   CTA tile 128(m) x 128(n), TK=16, 4m x 8n micro-tile per thread.
//   psp[m,n] = chunked_sum_k X[m,k]*W[n,k] + bias[n],  X[m,k] = in[b,k,t],
//   m = b*64 + t. Epilogue: psp staged in smem, 256 threads scan (b,n)
//   columns over all 64 timesteps, spikes written straight to d_out.
// ---------------------------------------------------------------------------
#define TM 128
#define TN 128
#define TK 16
#define NTHREADS 512
#define LDAB 132   // smem row pitch for As/Bs (floats), 16B-aligned
#define LDP  132   // psp stage pitch: multiple of 4 (float4-aligned stores)

#define AB_FLOATS (2 * TK * LDAB)          // 4224 floats per operand
#define PS_FLOATS (TM * LDP)               // 16896 floats
#define ARENA_BYTES (PS_FLOATS * 4)        // 67584 B  (> 2*AB_FLOATS*4)

__global__ __launch_bounds__(NTHREADS, 1)
void k_gemm_fused(const float* __restrict__ in,
                  const float* __restrict__ W,
                  const float* __restrict__ bias,
                  const float* __restrict__ decay,
                  float* __restrict__ out,
                  int write_vfinal) {
    extern __shared__ float smem[];
    float* As = smem;                 // [2][TK][LDAB]
    float* Bs = smem + AB_FLOATS;     // [2][TK][LDAB]

    const int tid = threadIdx.x;
    const int m0  = blockIdx.y * TM;
    const int n0  = blockIdx.x * TN;

    // ---- A loader: 512 threads cover 16k x 32(m/4): 1 float4 each ----
    const int kkA  = tid >> 5;             // 0..15
    const int lm4  = (tid & 31) * 4;       // 0..124
    const int bA   = (m0 + lm4) >> 6;      // batch
    const int tA   = (m0 + lm4) & 63;      // time
    const float* aptr = in + ((size_t)bA * DD + kkA) * TT + tA;

    // ---- B loader: 512 threads cover 128(n) x 4(k/4): 1 float4 each ----
    const int lnB  = tid >> 2;             // 0..127
    const int kc4  = (tid & 3) * 4;        // 0,4,8,12
    const float* wptr = W + (size_t)(n0 + lnB) * DD + kc4;

    // ---- compute map: 16(tx) x 32(ty); thread owns 4m x 8n (4 f32x2) ----
    const int tx = tid & 15;               // n block: tx*8
    const int ty = tid >> 4;               // m block: ty*4

    ull acc2[4][4], blk2[4][4];
    const ull zero2 = 0ull;
#pragma unroll
    for (int i = 0; i < 4; ++i)
#pragma unroll
        for (int j = 0; j < 4; ++j) { acc2[i][j] = zero2; blk2[i][j] = zero2; }

    // prologue: prefetch tile 0 (1 float4 per operand per thread)
    float4 pa = *(const float4*)(aptr);
    float4 pw = *(const float4*)(wptr);

    const int NTILES = DD / TK;  // 128
    int buf = 0;

    for (int tile = 0; tile < NTILES; ++tile) {
        float* Ab = As + buf * (TK * LDAB);
        float* Bb = Bs + buf * (TK * LDAB);

        *(float4*)&Ab[kkA * LDAB + lm4] = pa;
        Bb[(kc4 + 0) * LDAB + lnB] = pw.x;
        Bb[(kc4 + 1) * LDAB + lnB] = pw.y;
        Bb[(kc4 + 2) * LDAB + lnB] = pw.z;
        Bb[(kc4 + 3) * LDAB + lnB] = pw.w;
        __syncthreads();

        if (tile + 1 < NTILES) {
            pa = *(const float4*)(aptr + (size_t)(tile + 1) * TK * TT);
            pw = *(const float4*)(wptr + (size_t)(tile + 1) * TK);
        }

#pragma unroll
        for (int kk = 0; kk < TK; ++kk) {
            // A: 4 m-values (one LDS.128, broadcast across tx lanes)
            const float4 a = *(const float4*)&Ab[kk * LDAB + ty * 4];
            // B: 8 n-values = 4 contiguous 64-bit pairs (two LDS.128)
            const ull* brow = (const ull*)&Bb[kk * LDAB + tx * 8];
            ull rb2[4];
            rb2[0] = brow[0];
            rb2[1] = brow[1];
            rb2[2] = brow[2];
            rb2[3] = brow[3];

            ull ra2[4];
            PACK2(ra2[0], a.x, a.x);
            PACK2(ra2[1], a.y, a.y);
            PACK2(ra2[2], a.z, a.z);
            PACK2(ra2[3], a.w, a.w);

#pragma unroll
            for (int i = 0; i < 4; ++i)
#pragma unroll
                for (int j = 0; j < 4; ++j)
                    FMA2(blk2[i][j], ra2[i], rb2[j]);
        }

        // chunk boundary every 64 k (= 4 tiles): plain fp32 add per lane
        if ((tile & 3) == 3) {
#pragma unroll
            for (int i = 0; i < 4; ++i)
#pragma unroll
                for (int j = 0; j < 4; ++j) {
                    ADD2(acc2[i][j], acc2[i][j], blk2[i][j]);
                    blk2[i][j] = zero2;
                }
        }

        buf ^= 1;
    }

    // ---- epilogue: stage psp (+bias) into smem, then fused LIF scan ----
    __syncthreads();                 // all warps done reading As/Bs
    float* Ps = smem;                // reuse arena: [TM][LDP]

#pragma unroll
    for (int i = 0; i < 4; ++i) {
        const int mloc = ty * 4 + i;
        const int n    = n0 + tx * 8;
        float v[8];
#pragma unroll
        for (int j = 0; j < 4; ++j) {
            UNPACK2(v[2 * j], v[2 * j + 1], acc2[i][j]);
        }
        float4 o0, o1;
        o0.x = __fadd_rn(v[0], bias[n + 0]);
        o0.y = __fadd_rn(v[1], bias[n + 1]);
        o0.z = __fadd_rn(v[2], bias[n + 2]);
        o0.w = __fadd_rn(v[3], bias[n + 3]);
        o1.x = __fadd_rn(v[4], bias[n + 4]);
        o1.y = __fadd_rn(v[5], bias[n + 5]);
        o1.z = __fadd_rn(v[6], bias[n + 6]);
        o1.w = __fadd_rn(v[7], bias[n + 7]);
        *(float4*)&Ps[mloc * LDP + tx * 8]     = o0;
        *(float4*)&Ps[mloc * LDP + tx * 8 + 4] = o1;
    }
    __syncthreads();

    // scan: threads 0..255 -> (b_loc, n_loc); full T column in smem
    if (tid < 256) {
        const int bloc = tid >> 7;
        const int nloc = tid & 127;
        const int ng   = n0 + nloc;
        const int bg   = (m0 >> 6) + bloc;

        const float dec = decay[ng];
        float v = 0.0f, s = 0.0f;
        float sp[TT];

        const float* col = Ps + (size_t)(bloc * 64) * LDP + nloc;
#pragma unroll
        for (int t = 0; t < TT; ++t) {
            float a = __fsub_rn(1.0f, s);
            float c = __fmul_rn(a, v);
            float d = __fmul_rn(c, dec);
            v = __fadd_rn(d, col[(size_t)t * LDP]);
            s = (v > 0.5f) ? 1.0f : 0.0f;
            sp[t] = s;
        }

        float* o = out + ((size_t)bg * NN + ng) * TT;
#pragma unroll
        for (int t = 0; t < TT; t += 4) {
            *(float4*)&o[t] = make_float4(sp[t], sp[t + 1], sp[t + 2], sp[t + 3]);
        }
        if (write_vfinal) {
            out[(size_t)BB * NN * TT + (size_t)bg * NN + ng] = v;
        }
    }
}

// ---------------------------------------------------------------------------
extern "C" void kernel_launch(void* const* d_in, const int* in_sizes, int n_in,
                              void* d_out, int out_size) {
    const float* input = (const float*)d_in[0];  // [B, D, T]
    const float* W     = (const float*)d_in[1];  // [N, D]
    const float* bias  = (const float*)d_in[2];  // [N]
    const float* decay = (const float*)d_in[3];  // [N]
    float* out = (float*)d_out;

    const int write_vfinal =
        (out_size >= (int)((size_t)BB * NN * TT + (size_t)BB * NN)) ? 1 : 0;

    // Opt in to >48KB dynamic smem (idempotent attribute set; not an alloc).
    cudaFuncSetAttribute(k_gemm_fused,
                         cudaFuncAttributeMaxDynamicSharedMemorySize,
                         ARENA_BYTES);

    dim3 grid(NN / TN, MM / TM);   // 16 x 64
    k_gemm_fused<<<grid, NTHREADS, ARENA_BYTES>>>(input, W, bias, decay, out,
                                                  write_vfinal);
}